// round 9
// baseline (speedup 1.0000x reference)
#include <cuda_runtime.h>
#include <cuda_fp16.h>
#include <math.h>

#define MAXN 50000
#define MAXE 800000
#define FDIM 128

// Scratch (__device__ globals: allocation-free per harness rules)
__device__ __align__(16) __half g_h[MAXN * FDIM];   // h = A @ W  (fp16 storage)
__device__ __align__(16) float g_agg[MAXN * FDIM];  // layer output (fp32)
__device__ __align__(16) float g_dinv[MAXN];
__device__ __align__(16) float g_z[MAXN];
__device__ int g_src[MAXE];
__device__ int g_dst[MAXE];
__device__ int g_csr_src[MAXE];
__device__ int g_cnt[MAXN];
__device__ int g_cur[MAXN];
__device__ int g_rowptr[MAXN + 1];
__device__ int g_bsum[64];
__device__ int g_boff[64];
__device__ int g_is64;

// ---------------------------------------------------------------------------
// Fused: zero in-degree counters + edge dtype detection (block 0)
// ---------------------------------------------------------------------------
__global__ void k_init(const int* __restrict__ w, int N) {
    int i = blockIdx.x * blockDim.x + threadIdx.x;
    if (i < N) g_cnt[i] = 0;
    if (blockIdx.x == 0) {
        __shared__ int any;
        if (threadIdx.x == 0) any = 0;
        __syncthreads();
        int idx = 2 * threadIdx.x + 1;
        if (idx < 512 && w[idx] != 0) any = 1;
        __syncthreads();
        if (threadIdx.x == 0) g_is64 = (any == 0);
    }
}

__global__ void k_convert_count(const void* __restrict__ ei, int E, int N) {
    int e = blockIdx.x * blockDim.x + threadIdx.x;
    if (e >= E) return;
    int s, d;
    if (g_is64) {
        const long long* p = (const long long*)ei;
        s = (int)p[e]; d = (int)p[E + e];
    } else {
        const int* p = (const int*)ei;
        s = p[e]; d = p[E + e];
    }
    g_src[e] = s;
    g_dst[e] = d;
    if ((unsigned)d < (unsigned)N) atomicAdd(&g_cnt[d], 1);
}

// ---------------------------------------------------------------------------
// Parallel 3-phase exclusive scan of g_cnt -> g_rowptr
// ---------------------------------------------------------------------------
__global__ void __launch_bounds__(1024) k_scan1(int N) {
    __shared__ int sh[1024];
    int t = threadIdx.x;
    int i = blockIdx.x * 1024 + t;
    int c = (i < N) ? g_cnt[i] : 0;
    sh[t] = c;
    __syncthreads();
#pragma unroll
    for (int off = 1; off < 1024; off <<= 1) {
        int v = (t >= off) ? sh[t - off] : 0;
        __syncthreads();
        sh[t] += v;
        __syncthreads();
    }
    if (i < N) {
        g_rowptr[i] = sh[t] - c;
        g_dinv[i] = rsqrtf(1.0f + (float)c);
        g_cur[i] = 0;
    }
    if (t == 1023) g_bsum[blockIdx.x] = sh[1023];
}

__global__ void __launch_bounds__(64) k_scan2(int nb, int N) {
    __shared__ int sh[64];
    int t = threadIdx.x;
    int v = (t < nb) ? g_bsum[t] : 0;
    sh[t] = v;
    __syncthreads();
#pragma unroll
    for (int off = 1; off < 64; off <<= 1) {
        int u = (t >= off) ? sh[t - off] : 0;
        __syncthreads();
        sh[t] += u;
        __syncthreads();
    }
    if (t < nb) g_boff[t] = sh[t] - v;
    if (t == 63) g_rowptr[N] = sh[63];
}

__global__ void __launch_bounds__(1024) k_scan3(int N) {
    int i = blockIdx.x * 1024 + threadIdx.x;
    if (i < N) g_rowptr[i] += g_boff[blockIdx.x];
}

__global__ void k_fill(int E, int N) {
    int e = blockIdx.x * blockDim.x + threadIdx.x;
    if (e >= E) return;
    int s = g_src[e];
    int d = g_dst[e];
    if ((unsigned)s >= (unsigned)N || (unsigned)d >= (unsigned)N) return;
    int pos = g_rowptr[d] + atomicAdd(&g_cur[d], 1);
    g_csr_src[pos] = s;
}

// ---------------------------------------------------------------------------
// GEMM: g_h[N,128] = A[N,128] @ W[128,128]  (fp32 compute, fp16 store)
// MODE 0: A = concat(x_i, x_j); MODE 1: A = relu(g_agg)
// ---------------------------------------------------------------------------
template <int MODE>
__global__ void __launch_bounds__(128)
k_gemm(const float* __restrict__ A0, const float* __restrict__ A1,
       const float* __restrict__ W, int N)
{
    __shared__ float As[16][64];
    __shared__ float Bs[16][128];

    const int tid = threadIdx.x;
    const int tmb = (tid >> 4) * 8;
    const int tnb = (tid & 15) * 8;
    const int rowBase = blockIdx.x * 64;

    float acc[8][8];
#pragma unroll
    for (int i = 0; i < 8; i++)
#pragma unroll
        for (int j = 0; j < 8; j++) acc[i][j] = 0.0f;

    for (int kk = 0; kk < 128; kk += 16) {
#pragma unroll
        for (int t = 0; t < 2; t++) {
            int id = tid * 2 + t;
            int r = id >> 2, c4 = id & 3;
            int grow = rowBase + r;
            int gcol = kk + c4 * 4;
            float4 v = make_float4(0.f, 0.f, 0.f, 0.f);
            if (grow < N) {
                if (MODE == 0) {
                    const float* base = (gcol < 64)
                        ? (A0 + (size_t)grow * 64 + gcol)
                        : (A1 + (size_t)grow * 64 + (gcol - 64));
                    v = *(const float4*)base;
                } else {
                    v = *(const float4*)(g_agg + (size_t)grow * 128 + gcol);
                    v.x = fmaxf(v.x, 0.f); v.y = fmaxf(v.y, 0.f);
                    v.z = fmaxf(v.z, 0.f); v.w = fmaxf(v.w, 0.f);
                }
            }
            As[c4 * 4 + 0][r] = v.x;
            As[c4 * 4 + 1][r] = v.y;
            As[c4 * 4 + 2][r] = v.z;
            As[c4 * 4 + 3][r] = v.w;
        }
#pragma unroll
        for (int t = 0; t < 4; t++) {
            int id = tid * 4 + t;
            int k = id >> 5, c4 = id & 31;
            float4 v = *(const float4*)(W + (size_t)(kk + k) * 128 + c4 * 4);
            *(float4*)&Bs[k][c4 * 4] = v;
        }
        __syncthreads();

#pragma unroll
        for (int k = 0; k < 16; k++) {
            float a[8], b[8];
            *(float4*)&a[0] = *(const float4*)&As[k][tmb];
            *(float4*)&a[4] = *(const float4*)&As[k][tmb + 4];
            *(float4*)&b[0] = *(const float4*)&Bs[k][tnb];
            *(float4*)&b[4] = *(const float4*)&Bs[k][tnb + 4];
#pragma unroll
            for (int i = 0; i < 8; i++)
#pragma unroll
                for (int j = 0; j < 8; j++)
                    acc[i][j] = fmaf(a[i], b[j], acc[i][j]);
        }
        __syncthreads();
    }

    // epilogue: convert to fp16, one 16B store of 8 halfs per row-chunk
#pragma unroll
    for (int i = 0; i < 8; i++) {
        int row = rowBase + tmb + i;
        if (row >= N) continue;
        __half2 hbuf[4];
#pragma unroll
        for (int j = 0; j < 4; j++)
            hbuf[j] = __floats2half2_rn(acc[i][2 * j], acc[i][2 * j + 1]);
        *(uint4*)(g_h + (size_t)row * 128 + tnb) = *(const uint4*)&hbuf[0];
    }
}

// ---------------------------------------------------------------------------
// CSR aggregation: one warp per dst node; fp16 gathers (256B/row).
// EPI 0: store fp32 row to g_agg.
// EPI 1: z[d] = dot(relu(row), W3) -> g_z   (fused layer-3 projection)
// ---------------------------------------------------------------------------
template <int EPI>
__global__ void __launch_bounds__(256)
k_agg(const float* __restrict__ bias, const float* __restrict__ W3, int N)
{
    int idx = blockIdx.x * blockDim.x + threadIdx.x;
    int d = idx >> 5;
    int lane = idx & 31;
    if (d >= N) return;

    const float dd = g_dinv[d];
    const int col = lane * 4;           // 4 fp16 values per lane
    const unsigned FULL = 0xffffffffu;

    // self-loop + bias
    float2 raw = *(const float2*)(g_h + (size_t)d * 128 + col);
    float2 lo = __half22float2(*(const __half2*)&raw.x);
    float2 hi = __half22float2(*(const __half2*)&raw.y);
    float4 bb = *(const float4*)(bias + col);
    float d2 = dd * dd;
    float4 acc = make_float4(fmaf(lo.x, d2, bb.x), fmaf(lo.y, d2, bb.y),
                             fmaf(hi.x, d2, bb.z), fmaf(hi.y, d2, bb.w));

    int beg = g_rowptr[d];
    int end = g_rowptr[d + 1];
    for (int p = beg; p < end; p += 32) {
        int m = end - p;
        if (m > 32) m = 32;
        int s = 0;
        float ns = 0.0f;
        if (lane < m) {
            s = g_csr_src[p + lane];
            ns = g_dinv[s];
        }
        for (int j = 0; j < m; j++) {
            int sj = __shfl_sync(FULL, s, j);
            float nj = __shfl_sync(FULL, ns, j) * dd;
            float2 r = *(const float2*)(g_h + (size_t)sj * 128 + col);
            float2 vlo = __half22float2(*(const __half2*)&r.x);
            float2 vhi = __half22float2(*(const __half2*)&r.y);
            acc.x = fmaf(vlo.x, nj, acc.x);
            acc.y = fmaf(vlo.y, nj, acc.y);
            acc.z = fmaf(vhi.x, nj, acc.z);
            acc.w = fmaf(vhi.y, nj, acc.w);
        }
    }
    if (EPI == 0) {
        *(float4*)(g_agg + (size_t)d * 128 + col) = acc;
    } else {
        acc.x = fmaxf(acc.x, 0.f); acc.y = fmaxf(acc.y, 0.f);
        acc.z = fmaxf(acc.z, 0.f); acc.w = fmaxf(acc.w, 0.f);
        float4 w = *(const float4*)(W3 + col);
        float sdot = acc.x * w.x + acc.y * w.y + acc.z * w.z + acc.w * w.w;
#pragma unroll
        for (int o = 16; o > 0; o >>= 1) sdot += __shfl_xor_sync(FULL, sdot, o);
        if (lane == 0) g_z[d] = sdot;
    }
}

// Final: out[d] = sigmoid(z[d]*dd^2 + b3 + dd * sum_in z[s]*dinv[s])
__global__ void __launch_bounds__(256)
k_agg3(const float* __restrict__ b3, float* __restrict__ out, int N)
{
    int idx = blockIdx.x * blockDim.x + threadIdx.x;
    int d = idx >> 5;
    int lane = idx & 31;
    if (d >= N) return;
    int beg = g_rowptr[d];
    int end = g_rowptr[d + 1];
    float sum = 0.0f;
    for (int p = beg + lane; p < end; p += 32) {
        int s = g_csr_src[p];
        sum = fmaf(g_z[s], g_dinv[s], sum);
    }
#pragma unroll
    for (int o = 16; o > 0; o >>= 1) sum += __shfl_xor_sync(0xffffffffu, sum, o);
    if (lane == 0) {
        float dd = g_dinv[d];
        float val = fmaf(g_z[d], dd * dd, fmaf(dd, sum, b3[0]));
        out[d] = 1.0f / (1.0f + expf(-val));
    }
}

// ---------------------------------------------------------------------------
extern "C" void kernel_launch(void* const* d_in, const int* in_sizes, int n_in,
                              void* d_out, int out_size)
{
    const float* x_i = (const float*)d_in[0];
    const float* x_j = (const float*)d_in[1];
    const void*  ei  = d_in[2];
    const float* W1 = (const float*)d_in[3];
    const float* b1 = (const float*)d_in[4];
    const float* W2 = (const float*)d_in[5];
    const float* b2 = (const float*)d_in[6];
    const float* W3 = (const float*)d_in[7];
    const float* b3 = (const float*)d_in[8];
    float* out = (float*)d_out;

    const int N = in_sizes[0] / 64;
    const int E = in_sizes[2] / 2;

    const int TB = 256;
    const int NB = (N + 1023) / 1024;
    dim3 gN((N + TB - 1) / TB);
    dim3 gE((E + TB - 1) / TB);
    dim3 gGemm((N + 63) / 64);
    dim3 gWarpN((unsigned)(((long long)N * 32 + TB - 1) / TB));

    // CSR build
    k_init<<<gN, TB>>>((const int*)ei, N);
    k_convert_count<<<gE, TB>>>(ei, E, N);
    k_scan1<<<NB, 1024>>>(N);
    k_scan2<<<1, 64>>>(NB, N);
    k_scan3<<<NB, 1024>>>(N);
    k_fill<<<gE, TB>>>(E, N);

    // layer 1
    k_gemm<0><<<gGemm, 128>>>(x_i, x_j, W1, N);
    k_agg<0><<<gWarpN, TB>>>(b1, nullptr, N);

    // layer 2 (z fused into agg epilogue)
    k_gemm<1><<<gGemm, 128>>>(nullptr, nullptr, W2, N);
    k_agg<1><<<gWarpN, TB>>>(b2, W3, N);

    // layer 3 final
    k_agg3<<<gWarpN, TB>>>(b3, out, N);
}

// round 10
// speedup vs baseline: 1.7480x; 1.7480x over previous
#include <cuda_runtime.h>
#include <cuda_fp16.h>
#include <math.h>

#define MAXN 50000
#define MAXE 800000
#define FDIM 128

// Scratch (__device__ globals: allocation-free per harness rules)
__device__ __align__(16) __half g_h[MAXN * FDIM];    // h = A @ W (fp16)
__device__ __align__(16) __half g_a16[MAXN * FDIM];  // relu(layer output) (fp16)
__device__ __align__(16) __half g_w1t[FDIM * FDIM];  // W1^T fp16 [n][k]
__device__ __align__(16) __half g_w2t[FDIM * FDIM];  // W2^T fp16 [n][k]
__device__ __align__(16) float g_dinv[MAXN];
__device__ __align__(16) float g_z[MAXN];
__device__ int g_src[MAXE];
__device__ int g_dst[MAXE];
__device__ int g_csr_src[MAXE];
__device__ int g_cnt[MAXN];
__device__ int g_cur[MAXN];
__device__ int g_rowptr[MAXN + 1];
__device__ int g_bsum[64];
__device__ int g_boff[64];
__device__ int g_is64;

// ---------------------------------------------------------------------------
// Fused: zero in-degree counters + edge dtype detection (block 0)
// ---------------------------------------------------------------------------
__global__ void k_init(const int* __restrict__ w, int N) {
    int i = blockIdx.x * blockDim.x + threadIdx.x;
    if (i < N) g_cnt[i] = 0;
    if (blockIdx.x == 0) {
        __shared__ int any;
        if (threadIdx.x == 0) any = 0;
        __syncthreads();
        int idx = 2 * threadIdx.x + 1;
        if (idx < 512 && w[idx] != 0) any = 1;
        __syncthreads();
        if (threadIdx.x == 0) g_is64 = (any == 0);
    }
}

__global__ void k_convert_count(const void* __restrict__ ei, int E, int N) {
    int e = blockIdx.x * blockDim.x + threadIdx.x;
    if (e >= E) return;
    int s, d;
    if (g_is64) {
        const long long* p = (const long long*)ei;
        s = (int)p[e]; d = (int)p[E + e];
    } else {
        const int* p = (const int*)ei;
        s = p[e]; d = p[E + e];
    }
    g_src[e] = s;
    g_dst[e] = d;
    if ((unsigned)d < (unsigned)N) atomicAdd(&g_cnt[d], 1);
}

// ---------------------------------------------------------------------------
// Parallel 3-phase exclusive scan of g_cnt -> g_rowptr
// ---------------------------------------------------------------------------
__global__ void __launch_bounds__(1024) k_scan1(int N) {
    __shared__ int sh[1024];
    int t = threadIdx.x;
    int i = blockIdx.x * 1024 + t;
    int c = (i < N) ? g_cnt[i] : 0;
    sh[t] = c;
    __syncthreads();
#pragma unroll
    for (int off = 1; off < 1024; off <<= 1) {
        int v = (t >= off) ? sh[t - off] : 0;
        __syncthreads();
        sh[t] += v;
        __syncthreads();
    }
    if (i < N) {
        g_rowptr[i] = sh[t] - c;
        g_dinv[i] = rsqrtf(1.0f + (float)c);
        g_cur[i] = 0;
    }
    if (t == 1023) g_bsum[blockIdx.x] = sh[1023];
}

__global__ void __launch_bounds__(64) k_scan2(int nb, int N) {
    __shared__ int sh[64];
    int t = threadIdx.x;
    int v = (t < nb) ? g_bsum[t] : 0;
    sh[t] = v;
    __syncthreads();
#pragma unroll
    for (int off = 1; off < 64; off <<= 1) {
        int u = (t >= off) ? sh[t - off] : 0;
        __syncthreads();
        sh[t] += u;
        __syncthreads();
    }
    if (t < nb) g_boff[t] = sh[t] - v;
    if (t == 63) g_rowptr[N] = sh[63];
}

__global__ void __launch_bounds__(1024) k_scan3(int N) {
    int i = blockIdx.x * 1024 + threadIdx.x;
    if (i < N) g_rowptr[i] += g_boff[blockIdx.x];
}

__global__ void k_fill(int E, int N) {
    int e = blockIdx.x * blockDim.x + threadIdx.x;
    if (e >= E) return;
    int s = g_src[e];
    int d = g_dst[e];
    if ((unsigned)s >= (unsigned)N || (unsigned)d >= (unsigned)N) return;
    int pos = g_rowptr[d] + atomicAdd(&g_cur[d], 1);
    g_csr_src[pos] = s;
}

// ---------------------------------------------------------------------------
// Weight prep: W^T fp16 (coalesced read, scattered 2B write — tiny)
// ---------------------------------------------------------------------------
__global__ void k_wprep(const float* __restrict__ W1, const float* __restrict__ W2) {
    int k = blockIdx.x;       // 0..127
    int n = threadIdx.x;      // 0..127
    g_w1t[n * 128 + k] = __float2half_rn(W1[k * 128 + n]);
    g_w2t[n * 128 + k] = __float2half_rn(W2[k * 128 + n]);
}

// ---------------------------------------------------------------------------
// Tensor-core GEMM: g_h[N,128] = A[N,128] @ W[128,128]
// HMMA m16n8k16, fp16 in / fp32 accum, fp16 out.
// MODE 0: A = concat(x_i, x_j) fp32->fp16;  MODE 1: A = g_a16 (relu'd fp16)
// Block: 128 rows x 128 cols, 256 threads (8 warps x 16 rows), K in 2 stages of 64.
// ---------------------------------------------------------------------------
#define AS 72   // smem row stride in halfs (pad: conflict-free frag loads)

template <int MODE>
__global__ void __launch_bounds__(256)
k_gemm_tc(const float* __restrict__ A0, const float* __restrict__ A1, int N)
{
    __shared__ __half As[128 * AS];
    __shared__ __half Bs[128 * AS];   // B^T: Bs[n][k]

    const int tid = threadIdx.x;
    const int wid = tid >> 5;
    const int lane = tid & 31;
    const int r = lane >> 2;          // 0..7
    const int q = lane & 3;           // 0..3
    const int blockRow = blockIdx.x * 128;
    const __half* gw = (MODE == 0) ? g_w1t : g_w2t;

    float acc[16][4];
#pragma unroll
    for (int nt = 0; nt < 16; nt++)
#pragma unroll
        for (int j = 0; j < 4; j++) acc[nt][j] = 0.0f;

    for (int kb = 0; kb < 2; kb++) {
        // ---- load A stage (128 rows x 64 halfs)
        if (MODE == 0) {
            const float* src = kb ? A1 : A0;   // kb=0: x_i cols, kb=1: x_j cols
#pragma unroll
            for (int g = 0; g < 8; g++) {
                int idx = g * 256 + tid;       // 0..2047 quads
                int row = idx >> 4;
                int c4 = (idx & 15) * 4;
                int grow = blockRow + row;
                float4 v = make_float4(0.f, 0.f, 0.f, 0.f);
                if (grow < N) v = *(const float4*)(src + (size_t)grow * 64 + c4);
                __half2 h0 = __floats2half2_rn(v.x, v.y);
                __half2 h1 = __floats2half2_rn(v.z, v.w);
                uint2 pk = make_uint2(*(const unsigned*)&h0, *(const unsigned*)&h1);
                *(uint2*)&As[row * AS + c4] = pk;
            }
        } else {
#pragma unroll
            for (int g = 0; g < 8; g++) {
                int idx = g * 256 + tid;
                int row = idx >> 4;
                int c4 = (idx & 15) * 4;
                int grow = blockRow + row;
                uint2 v = make_uint2(0u, 0u);
                if (grow < N) v = *(const uint2*)(g_a16 + (size_t)grow * 128 + kb * 64 + c4);
                *(uint2*)&As[row * AS + c4] = v;
            }
        }
        // ---- load B stage (B^T: 128 n-rows x 64 k-halfs)
#pragma unroll
        for (int g = 0; g < 4; g++) {
            int idx = g * 256 + tid;           // 0..1023 chunks of 8 halfs
            int n = idx >> 3;
            int k8 = (idx & 7) * 8;
            *(uint4*)&Bs[n * AS + k8] = *(const uint4*)(gw + n * 128 + kb * 64 + k8);
        }
        __syncthreads();

        const __half* Ab = As + (wid * 16 + r) * AS + q * 2;
        const __half* Bb = Bs + r * AS + q * 2;
#pragma unroll
        for (int ks = 0; ks < 4; ks++) {
            unsigned aA = *(const unsigned*)(Ab + ks * 16);
            unsigned aB = *(const unsigned*)(Ab + 8 * AS + ks * 16);
            unsigned aC = *(const unsigned*)(Ab + ks * 16 + 8);
            unsigned aD = *(const unsigned*)(Ab + 8 * AS + ks * 16 + 8);
#pragma unroll
            for (int nt = 0; nt < 16; nt++) {
                unsigned b0 = *(const unsigned*)(Bb + nt * 8 * AS + ks * 16);
                unsigned b1 = *(const unsigned*)(Bb + nt * 8 * AS + ks * 16 + 8);
                asm volatile(
                    "mma.sync.aligned.m16n8k16.row.col.f32.f16.f16.f32 "
                    "{%0,%1,%2,%3}, {%4,%5,%6,%7}, {%8,%9}, {%0,%1,%2,%3};\n"
                    : "+f"(acc[nt][0]), "+f"(acc[nt][1]), "+f"(acc[nt][2]), "+f"(acc[nt][3])
                    : "r"(aA), "r"(aB), "r"(aC), "r"(aD), "r"(b0), "r"(b1));
            }
        }
        __syncthreads();
    }

    // ---- epilogue: fp16 store
    int row0 = blockRow + wid * 16 + r;
    int row1 = row0 + 8;
    if (row0 < N) {
#pragma unroll
        for (int nt = 0; nt < 16; nt++) {
            __half2 h = __floats2half2_rn(acc[nt][0], acc[nt][1]);
            *(__half2*)(g_h + (size_t)row0 * 128 + nt * 8 + q * 2) = h;
        }
    }
    if (row1 < N) {
#pragma unroll
        for (int nt = 0; nt < 16; nt++) {
            __half2 h = __floats2half2_rn(acc[nt][2], acc[nt][3]);
            *(__half2*)(g_h + (size_t)row1 * 128 + nt * 8 + q * 2) = h;
        }
    }
}

// ---------------------------------------------------------------------------
// CSR aggregation: one warp per dst node; fp16 gathers (256B/row).
// EPI 0: store relu(row) as fp16 to g_a16 (feeds next GEMM).
// EPI 1: z[d] = dot(relu(row), W3) -> g_z   (fused layer-3 projection)
// ---------------------------------------------------------------------------
template <int EPI>
__global__ void __launch_bounds__(256)
k_agg(const float* __restrict__ bias, const float* __restrict__ W3, int N)
{
    int idx = blockIdx.x * blockDim.x + threadIdx.x;
    int d = idx >> 5;
    int lane = idx & 31;
    if (d >= N) return;

    const float dd = g_dinv[d];
    const int col = lane * 4;           // 4 fp16 values per lane
    const unsigned FULL = 0xffffffffu;

    // self-loop + bias
    float2 raw = *(const float2*)(g_h + (size_t)d * 128 + col);
    float2 lo = __half22float2(*(const __half2*)&raw.x);
    float2 hi = __half22float2(*(const __half2*)&raw.y);
    float4 bb = *(const float4*)(bias + col);
    float d2 = dd * dd;
    float4 acc = make_float4(fmaf(lo.x, d2, bb.x), fmaf(lo.y, d2, bb.y),
                             fmaf(hi.x, d2, bb.z), fmaf(hi.y, d2, bb.w));

    int beg = g_rowptr[d];
    int end = g_rowptr[d + 1];
    for (int p = beg; p < end; p += 32) {
        int m = end - p;
        if (m > 32) m = 32;
        int s = 0;
        float ns = 0.0f;
        if (lane < m) {
            s = g_csr_src[p + lane];
            ns = g_dinv[s];
        }
        for (int j = 0; j < m; j++) {
            int sj = __shfl_sync(FULL, s, j);
            float nj = __shfl_sync(FULL, ns, j) * dd;
            float2 rr = *(const float2*)(g_h + (size_t)sj * 128 + col);
            float2 vlo = __half22float2(*(const __half2*)&rr.x);
            float2 vhi = __half22float2(*(const __half2*)&rr.y);
            acc.x = fmaf(vlo.x, nj, acc.x);
            acc.y = fmaf(vlo.y, nj, acc.y);
            acc.z = fmaf(vhi.x, nj, acc.z);
            acc.w = fmaf(vhi.y, nj, acc.w);
        }
    }
    if (EPI == 0) {
        __half2 h0 = __floats2half2_rn(fmaxf(acc.x, 0.f), fmaxf(acc.y, 0.f));
        __half2 h1 = __floats2half2_rn(fmaxf(acc.z, 0.f), fmaxf(acc.w, 0.f));
        uint2 pk = make_uint2(*(const unsigned*)&h0, *(const unsigned*)&h1);
        *(uint2*)(g_a16 + (size_t)d * 128 + col) = pk;
    } else {
        acc.x = fmaxf(acc.x, 0.f); acc.y = fmaxf(acc.y, 0.f);
        acc.z = fmaxf(acc.z, 0.f); acc.w = fmaxf(acc.w, 0.f);
        float4 w = *(const float4*)(W3 + col);
        float sdot = acc.x * w.x + acc.y * w.y + acc.z * w.z + acc.w * w.w;
#pragma unroll
        for (int o = 16; o > 0; o >>= 1) sdot += __shfl_xor_sync(FULL, sdot, o);
        if (lane == 0) g_z[d] = sdot;
    }
}

// Final: out[d] = sigmoid(z[d]*dd^2 + b3 + dd * sum_in z[s]*dinv[s])
__global__ void __launch_bounds__(256)
k_agg3(const float* __restrict__ b3, float* __restrict__ out, int N)
{
    int idx = blockIdx.x * blockDim.x + threadIdx.x;
    int d = idx >> 5;
    int lane = idx & 31;
    if (d >= N) return;
    int beg = g_rowptr[d];
    int end = g_rowptr[d + 1];
    float sum = 0.0f;
    for (int p = beg + lane; p < end; p += 32) {
        int s = g_csr_src[p];
        sum = fmaf(g_z[s], g_dinv[s], sum);
    }
#pragma unroll
    for (int o = 16; o > 0; o >>= 1) sum += __shfl_xor_sync(0xffffffffu, sum, o);
    if (lane == 0) {
        float dd = g_dinv[d];
        float val = fmaf(g_z[d], dd * dd, fmaf(dd, sum, b3[0]));
        out[d] = 1.0f / (1.0f + expf(-val));
    }
}

// ---------------------------------------------------------------------------
extern "C" void kernel_launch(void* const* d_in, const int* in_sizes, int n_in,
                              void* d_out, int out_size)
{
    const float* x_i = (const float*)d_in[0];
    const float* x_j = (const float*)d_in[1];
    const void*  ei  = d_in[2];
    const float* W1 = (const float*)d_in[3];
    const float* b1 = (const float*)d_in[4];
    const float* W2 = (const float*)d_in[5];
    const float* b2 = (const float*)d_in[6];
    const float* W3 = (const float*)d_in[7];
    const float* b3 = (const float*)d_in[8];
    float* out = (float*)d_out;

    const int N = in_sizes[0] / 64;
    const int E = in_sizes[2] / 2;

    const int TB = 256;
    const int NB = (N + 1023) / 1024;
    dim3 gN((N + TB - 1) / TB);
    dim3 gE((E + TB - 1) / TB);
    dim3 gGemm((N + 127) / 128);
    dim3 gWarpN((unsigned)(((long long)N * 32 + TB - 1) / TB));

    // CSR build + weight prep
    k_init<<<gN, TB>>>((const int*)ei, N);
    k_convert_count<<<gE, TB>>>(ei, E, N);
    k_scan1<<<NB, 1024>>>(N);
    k_scan2<<<1, 64>>>(NB, N);
    k_scan3<<<NB, 1024>>>(N);
    k_fill<<<gE, TB>>>(E, N);
    k_wprep<<<128, 128>>>(W1, W2);

    // layer 1
    k_gemm_tc<0><<<gGemm, 256>>>(x_i, x_j, N);
    k_agg<0><<<gWarpN, TB>>>(b1, nullptr, N);

    // layer 2 (z fused into agg epilogue)
    k_gemm_tc<1><<<gGemm, 256>>>(nullptr, nullptr, N);
    k_agg<1><<<gWarpN, TB>>>(b2, W3, N);

    // layer 3 final
    k_agg3<<<gWarpN, TB>>>(b3, out, N);
}

// round 11
// speedup vs baseline: 1.7744x; 1.0151x over previous
#include <cuda_runtime.h>
#include <cuda_fp16.h>
#include <math.h>

#define MAXN 50000
#define MAXE 800000
#define FDIM 128

// Scratch (__device__ globals: allocation-free per harness rules)
__device__ __align__(16) __half g_h[MAXN * FDIM];    // h = A @ W (fp16)
__device__ __align__(16) __half g_a16[MAXN * FDIM];  // relu(layer output) (fp16)
__device__ __align__(16) __half g_w1t[FDIM * FDIM];  // W1^T fp16 [n][k]
__device__ __align__(16) __half g_w2t[FDIM * FDIM];  // W2^T fp16 [n][k]
__device__ __align__(16) float g_dinv[MAXN];
__device__ __align__(16) float g_z[MAXN];
__device__ int g_src[MAXE];
__device__ int g_dst[MAXE];
__device__ int g_csr_src[MAXE];
__device__ int g_cnt[MAXN];
__device__ int g_cur[MAXN];
__device__ int g_rowptr[MAXN + 1];
__device__ int g_bsum[64];
__device__ int g_boff[64];
__device__ int g_is64;

// ---------------------------------------------------------------------------
// Fused: zero in-degree counters + edge dtype detection (block 0)
// ---------------------------------------------------------------------------
__global__ void k_init(const int* __restrict__ w, int N) {
    int i = blockIdx.x * blockDim.x + threadIdx.x;
    if (i < N) g_cnt[i] = 0;
    if (blockIdx.x == 0) {
        __shared__ int any;
        if (threadIdx.x == 0) any = 0;
        __syncthreads();
        int idx = 2 * threadIdx.x + 1;
        if (idx < 512 && w[idx] != 0) any = 1;
        __syncthreads();
        if (threadIdx.x == 0) g_is64 = (any == 0);
    }
}

__global__ void k_convert_count(const void* __restrict__ ei, int E, int N) {
    int e = blockIdx.x * blockDim.x + threadIdx.x;
    if (e >= E) return;
    int s, d;
    if (g_is64) {
        const long long* p = (const long long*)ei;
        s = (int)p[e]; d = (int)p[E + e];
    } else {
        const int* p = (const int*)ei;
        s = p[e]; d = p[E + e];
    }
    g_src[e] = s;
    g_dst[e] = d;
    if ((unsigned)d < (unsigned)N) atomicAdd(&g_cnt[d], 1);
}

// ---------------------------------------------------------------------------
// Parallel 3-phase exclusive scan of g_cnt -> g_rowptr
// ---------------------------------------------------------------------------
__global__ void __launch_bounds__(1024) k_scan1(int N) {
    __shared__ int sh[1024];
    int t = threadIdx.x;
    int i = blockIdx.x * 1024 + t;
    int c = (i < N) ? g_cnt[i] : 0;
    sh[t] = c;
    __syncthreads();
#pragma unroll
    for (int off = 1; off < 1024; off <<= 1) {
        int v = (t >= off) ? sh[t - off] : 0;
        __syncthreads();
        sh[t] += v;
        __syncthreads();
    }
    if (i < N) {
        g_rowptr[i] = sh[t] - c;
        g_dinv[i] = rsqrtf(1.0f + (float)c);
        g_cur[i] = 0;
    }
    if (t == 1023) g_bsum[blockIdx.x] = sh[1023];
}

__global__ void __launch_bounds__(64) k_scan2(int nb, int N) {
    __shared__ int sh[64];
    int t = threadIdx.x;
    int v = (t < nb) ? g_bsum[t] : 0;
    sh[t] = v;
    __syncthreads();
#pragma unroll
    for (int off = 1; off < 64; off <<= 1) {
        int u = (t >= off) ? sh[t - off] : 0;
        __syncthreads();
        sh[t] += u;
        __syncthreads();
    }
    if (t < nb) g_boff[t] = sh[t] - v;
    if (t == 63) g_rowptr[N] = sh[63];
}

__global__ void __launch_bounds__(1024) k_scan3(int N) {
    int i = blockIdx.x * 1024 + threadIdx.x;
    if (i < N) g_rowptr[i] += g_boff[blockIdx.x];
}

__global__ void k_fill(int E, int N) {
    int e = blockIdx.x * blockDim.x + threadIdx.x;
    if (e >= E) return;
    int s = g_src[e];
    int d = g_dst[e];
    if ((unsigned)s >= (unsigned)N || (unsigned)d >= (unsigned)N) return;
    int pos = g_rowptr[d] + atomicAdd(&g_cur[d], 1);
    g_csr_src[pos] = s;
}

// ---------------------------------------------------------------------------
// Weight prep: W^T fp16 (coalesced read, scattered 2B write — tiny)
// ---------------------------------------------------------------------------
__global__ void k_wprep(const float* __restrict__ W1, const float* __restrict__ W2) {
    int k = blockIdx.x;       // 0..127
    int n = threadIdx.x;      // 0..127
    g_w1t[n * 128 + k] = __float2half_rn(W1[k * 128 + n]);
    g_w2t[n * 128 + k] = __float2half_rn(W2[k * 128 + n]);
}

// ---------------------------------------------------------------------------
// Tensor-core GEMM: g_h[N,128] = A[N,128] @ W[128,128]
// HMMA m16n8k16, fp16 in / fp32 accum, fp16 out.
// MODE 0: A = concat(x_i, x_j) fp32->fp16;  MODE 1: A = g_a16 (relu'd fp16)
// Block: 128 rows x 128 cols, 256 threads (8 warps x 16 rows), K in 2 stages of 64.
// ---------------------------------------------------------------------------
#define AS 72   // smem row stride in halfs (pad: conflict-free frag loads)

template <int MODE>
__global__ void __launch_bounds__(256)
k_gemm_tc(const float* __restrict__ A0, const float* __restrict__ A1, int N)
{
    __shared__ __half As[128 * AS];
    __shared__ __half Bs[128 * AS];   // B^T: Bs[n][k]

    const int tid = threadIdx.x;
    const int wid = tid >> 5;
    const int lane = tid & 31;
    const int r = lane >> 2;          // 0..7
    const int q = lane & 3;           // 0..3
    const int blockRow = blockIdx.x * 128;
    const __half* gw = (MODE == 0) ? g_w1t : g_w2t;

    float acc[16][4];
#pragma unroll
    for (int nt = 0; nt < 16; nt++)
#pragma unroll
        for (int j = 0; j < 4; j++) acc[nt][j] = 0.0f;

    for (int kb = 0; kb < 2; kb++) {
        // ---- load A stage (128 rows x 64 halfs)
        if (MODE == 0) {
            const float* src = kb ? A1 : A0;   // kb=0: x_i cols, kb=1: x_j cols
#pragma unroll
            for (int g = 0; g < 8; g++) {
                int idx = g * 256 + tid;       // 0..2047 quads
                int row = idx >> 4;
                int c4 = (idx & 15) * 4;
                int grow = blockRow + row;
                float4 v = make_float4(0.f, 0.f, 0.f, 0.f);
                if (grow < N) v = *(const float4*)(src + (size_t)grow * 64 + c4);
                __half2 h0 = __floats2half2_rn(v.x, v.y);
                __half2 h1 = __floats2half2_rn(v.z, v.w);
                uint2 pk = make_uint2(*(const unsigned*)&h0, *(const unsigned*)&h1);
                *(uint2*)&As[row * AS + c4] = pk;
            }
        } else {
#pragma unroll
            for (int g = 0; g < 8; g++) {
                int idx = g * 256 + tid;
                int row = idx >> 4;
                int c4 = (idx & 15) * 4;
                int grow = blockRow + row;
                uint2 v = make_uint2(0u, 0u);
                if (grow < N) v = *(const uint2*)(g_a16 + (size_t)grow * 128 + kb * 64 + c4);
                *(uint2*)&As[row * AS + c4] = v;
            }
        }
        // ---- load B stage (B^T: 128 n-rows x 64 k-halfs)
#pragma unroll
        for (int g = 0; g < 4; g++) {
            int idx = g * 256 + tid;           // 0..1023 chunks of 8 halfs
            int n = idx >> 3;
            int k8 = (idx & 7) * 8;
            *(uint4*)&Bs[n * AS + k8] = *(const uint4*)(gw + n * 128 + kb * 64 + k8);
        }
        __syncthreads();

        const __half* Ab = As + (wid * 16 + r) * AS + q * 2;
        const __half* Bb = Bs + r * AS + q * 2;
#pragma unroll
        for (int ks = 0; ks < 4; ks++) {
            unsigned aA = *(const unsigned*)(Ab + ks * 16);
            unsigned aB = *(const unsigned*)(Ab + 8 * AS + ks * 16);
            unsigned aC = *(const unsigned*)(Ab + ks * 16 + 8);
            unsigned aD = *(const unsigned*)(Ab + 8 * AS + ks * 16 + 8);
#pragma unroll
            for (int nt = 0; nt < 16; nt++) {
                unsigned b0 = *(const unsigned*)(Bb + nt * 8 * AS + ks * 16);
                unsigned b1 = *(const unsigned*)(Bb + nt * 8 * AS + ks * 16 + 8);
                asm volatile(
                    "mma.sync.aligned.m16n8k16.row.col.f32.f16.f16.f32 "
                    "{%0,%1,%2,%3}, {%4,%5,%6,%7}, {%8,%9}, {%0,%1,%2,%3};\n"
                    : "+f"(acc[nt][0]), "+f"(acc[nt][1]), "+f"(acc[nt][2]), "+f"(acc[nt][3])
                    : "r"(aA), "r"(aB), "r"(aC), "r"(aD), "r"(b0), "r"(b1));
            }
        }
        __syncthreads();
    }

    // ---- epilogue: fp16 store
    int row0 = blockRow + wid * 16 + r;
    int row1 = row0 + 8;
    if (row0 < N) {
#pragma unroll
        for (int nt = 0; nt < 16; nt++) {
            __half2 h = __floats2half2_rn(acc[nt][0], acc[nt][1]);
            *(__half2*)(g_h + (size_t)row0 * 128 + nt * 8 + q * 2) = h;
        }
    }
    if (row1 < N) {
#pragma unroll
        for (int nt = 0; nt < 16; nt++) {
            __half2 h = __floats2half2_rn(acc[nt][2], acc[nt][3]);
            *(__half2*)(g_h + (size_t)row1 * 128 + nt * 8 + q * 2) = h;
        }
    }
}

// ---------------------------------------------------------------------------
// CSR aggregation: one warp per dst node; fp16 gathers (256B/row).
// EPI 0: store relu(row) as fp16 to g_a16 (feeds next GEMM).
// EPI 1: z[d] = dot(relu(row), W3) -> g_z   (fused layer-3 projection)
// ---------------------------------------------------------------------------
template <int EPI>
__global__ void __launch_bounds__(256)
k_agg(const float* __restrict__ bias, const float* __restrict__ W3, int N)
{
    int idx = blockIdx.x * blockDim.x + threadIdx.x;
    int d = idx >> 5;
    int lane = idx & 31;
    if (d >= N) return;

    const float dd = g_dinv[d];
    const int col = lane * 4;           // 4 fp16 values per lane
    const unsigned FULL = 0xffffffffu;

    // self-loop + bias
    float2 raw = *(const float2*)(g_h + (size_t)d * 128 + col);
    float2 lo = __half22float2(*(const __half2*)&raw.x);
    float2 hi = __half22float2(*(const __half2*)&raw.y);
    float4 bb = *(const float4*)(bias + col);
    float d2 = dd * dd;
    float4 acc = make_float4(fmaf(lo.x, d2, bb.x), fmaf(lo.y, d2, bb.y),
                             fmaf(hi.x, d2, bb.z), fmaf(hi.y, d2, bb.w));

    int beg = g_rowptr[d];
    int end = g_rowptr[d + 1];
    for (int p = beg; p < end; p += 32) {
        int m = end - p;
        if (m > 32) m = 32;
        int s = 0;
        float ns = 0.0f;
        if (lane < m) {
            s = g_csr_src[p + lane];
            ns = g_dinv[s];
        }
        for (int j = 0; j < m; j++) {
            int sj = __shfl_sync(FULL, s, j);
            float nj = __shfl_sync(FULL, ns, j) * dd;
            float2 rr = *(const float2*)(g_h + (size_t)sj * 128 + col);
            float2 vlo = __half22float2(*(const __half2*)&rr.x);
            float2 vhi = __half22float2(*(const __half2*)&rr.y);
            acc.x = fmaf(vlo.x, nj, acc.x);
            acc.y = fmaf(vlo.y, nj, acc.y);
            acc.z = fmaf(vhi.x, nj, acc.z);
            acc.w = fmaf(vhi.y, nj, acc.w);
        }
    }
    if (EPI == 0) {
        __half2 h0 = __floats2half2_rn(fmaxf(acc.x, 0.f), fmaxf(acc.y, 0.f));
        __half2 h1 = __floats2half2_rn(fmaxf(acc.z, 0.f), fmaxf(acc.w, 0.f));
        uint2 pk = make_uint2(*(const unsigned*)&h0, *(const unsigned*)&h1);
        *(uint2*)(g_a16 + (size_t)d * 128 + col) = pk;
    } else {
        acc.x = fmaxf(acc.x, 0.f); acc.y = fmaxf(acc.y, 0.f);
        acc.z = fmaxf(acc.z, 0.f); acc.w = fmaxf(acc.w, 0.f);
        float4 w = *(const float4*)(W3 + col);
        float sdot = acc.x * w.x + acc.y * w.y + acc.z * w.z + acc.w * w.w;
#pragma unroll
        for (int o = 16; o > 0; o >>= 1) sdot += __shfl_xor_sync(FULL, sdot, o);
        if (lane == 0) g_z[d] = sdot;
    }
}

// Final: out[d] = sigmoid(z[d]*dd^2 + b3 + dd * sum_in z[s]*dinv[s])
__global__ void __launch_bounds__(256)
k_agg3(const float* __restrict__ b3, float* __restrict__ out, int N)
{
    int idx = blockIdx.x * blockDim.x + threadIdx.x;
    int d = idx >> 5;
    int lane = idx & 31;
    if (d >= N) return;
    int beg = g_rowptr[d];
    int end = g_rowptr[d + 1];
    float sum = 0.0f;
    for (int p = beg + lane; p < end; p += 32) {
        int s = g_csr_src[p];
        sum = fmaf(g_z[s], g_dinv[s], sum);
    }
#pragma unroll
    for (int o = 16; o > 0; o >>= 1) sum += __shfl_xor_sync(0xffffffffu, sum, o);
    if (lane == 0) {
        float dd = g_dinv[d];
        float val = fmaf(g_z[d], dd * dd, fmaf(dd, sum, b3[0]));
        out[d] = 1.0f / (1.0f + expf(-val));
    }
}

// ---------------------------------------------------------------------------
extern "C" void kernel_launch(void* const* d_in, const int* in_sizes, int n_in,
                              void* d_out, int out_size)
{
    const float* x_i = (const float*)d_in[0];
    const float* x_j = (const float*)d_in[1];
    const void*  ei  = d_in[2];
    const float* W1 = (const float*)d_in[3];
    const float* b1 = (const float*)d_in[4];
    const float* W2 = (const float*)d_in[5];
    const float* b2 = (const float*)d_in[6];
    const float* W3 = (const float*)d_in[7];
    const float* b3 = (const float*)d_in[8];
    float* out = (float*)d_out;

    const int N = in_sizes[0] / 64;
    const int E = in_sizes[2] / 2;

    const int TB = 256;
    const int NB = (N + 1023) / 1024;
    dim3 gN((N + TB - 1) / TB);
    dim3 gE((E + TB - 1) / TB);
    dim3 gGemm((N + 127) / 128);
    dim3 gWarpN((unsigned)(((long long)N * 32 + TB - 1) / TB));

    // CSR build + weight prep
    k_init<<<gN, TB>>>((const int*)ei, N);
    k_convert_count<<<gE, TB>>>(ei, E, N);
    k_scan1<<<NB, 1024>>>(N);
    k_scan2<<<1, 64>>>(NB, N);
    k_scan3<<<NB, 1024>>>(N);
    k_fill<<<gE, TB>>>(E, N);
    k_wprep<<<128, 128>>>(W1, W2);

    // layer 1
    k_gemm_tc<0><<<gGemm, 256>>>(x_i, x_j, N);
    k_agg<0><<<gWarpN, TB>>>(b1, nullptr, N);

    // layer 2 (z fused into agg epilogue)
    k_gemm_tc<1><<<gGemm, 256>>>(nullptr, nullptr, N);
    k_agg<1><<<gWarpN, TB>>>(b2, W3, N);

    // layer 3 final
    k_agg3<<<gWarpN, TB>>>(b3, out, N);
}